// round 6
// baseline (speedup 1.0000x reference)
#include <cuda_runtime.h>
#include <cuda_bf16.h>

#define N_NODES 100000
#define N_EDGES 3200000

// Interleaved accumulators for the two W1-column projections of the segment
// sum: g_acc[2*n] = proj onto W1 col 0, g_acc[2*n+1] = proj onto W1 col 1.
// Zero-initialized at module load; node_kernel self-cleans after reading, so
// every kernel_launch (including CUDA-graph replays) starts from zero.
// Padded to a multiple of 8 floats so the node kernel's float4 tail is safe.
__device__ float g_acc[2 * N_NODES + 8];

// ---------------------------------------------------------------------------
// Edge kernel: for each edge, project its 16-dim feature onto W1[3:19, 0] and
// W1[3:19, 1] and reduce into the destination node's slot with ONE vector
// red.global.add.v2.f32. Linearity: (sum_e edge_attr_e) . w ==
// sum_e (edge_attr_e . w); relu is applied only after the full segment sum.
// ---------------------------------------------------------------------------
__global__ __launch_bounds__(256, 8)
void edge_kernel(const float* __restrict__ edge_attr,
                 const int* __restrict__ col,
                 const float* __restrict__ W1) {
    __shared__ float w0[16];
    __shared__ float w1[16];
    if (threadIdx.x < 16) {
        // W1 is (19, 2) row-major; edge features occupy rows 3..18
        w0[threadIdx.x] = W1[(3 + threadIdx.x) * 2 + 0];
        w1[threadIdx.x] = W1[(3 + threadIdx.x) * 2 + 1];
    }
    __syncthreads();

    int e = blockIdx.x * blockDim.x + threadIdx.x;
    if (e >= N_EDGES) return;

    const float4* ea = reinterpret_cast<const float4*>(edge_attr) + (size_t)e * 4;
    int c = __ldcs(&col[e]);
    // Streaming (evict-first) loads: edge_attr is read exactly once and must
    // not evict the hot 800KB accumulator array from L2.
    float4 a0 = __ldcs(ea + 0);
    float4 a1 = __ldcs(ea + 1);
    float4 a2 = __ldcs(ea + 2);
    float4 a3 = __ldcs(ea + 3);

    float s0, s1;
    s0 = fmaf(a0.x, w0[0], fmaf(a0.y, w0[1], fmaf(a0.z, w0[2], a0.w * w0[3])));
    s0 = fmaf(a1.x, w0[4], fmaf(a1.y, w0[5], fmaf(a1.z, w0[6], fmaf(a1.w, w0[7], s0))));
    s0 = fmaf(a2.x, w0[8], fmaf(a2.y, w0[9], fmaf(a2.z, w0[10], fmaf(a2.w, w0[11], s0))));
    s0 = fmaf(a3.x, w0[12], fmaf(a3.y, w0[13], fmaf(a3.z, w0[14], fmaf(a3.w, w0[15], s0))));

    s1 = fmaf(a0.x, w1[0], fmaf(a0.y, w1[1], fmaf(a0.z, w1[2], a0.w * w1[3])));
    s1 = fmaf(a1.x, w1[4], fmaf(a1.y, w1[5], fmaf(a1.z, w1[6], fmaf(a1.w, w1[7], s1))));
    s1 = fmaf(a2.x, w1[8], fmaf(a2.y, w1[9], fmaf(a2.z, w1[10], fmaf(a2.w, w1[11], s1))));
    s1 = fmaf(a3.x, w1[12], fmaf(a3.y, w1[13], fmaf(a3.z, w1[14], fmaf(a3.w, w1[15], s1))));

    asm volatile("red.global.add.v2.f32 [%0], {%1, %2};"
                 :: "l"(&g_acc[2 * c]), "f"(s0), "f"(s1)
                 : "memory");
}

// ---------------------------------------------------------------------------
// Node kernel: 4 nodes per thread, fully float4-vectorized (MLP=5 independent
// 16B loads per thread to hide DRAM latency; was latency-bound at MLP~2).
// Finishes MLP column 2 (cols 0,1 of the MLP output are dead — overwritten by
// n1 / n1_n2 which depend only on x), computes the analytic terms via hardware
// exp2, adds the x residual, self-cleans the accumulators.
// ---------------------------------------------------------------------------
__global__ __launch_bounds__(128, 8)
void node_kernel(const float* __restrict__ x,
                 const float* __restrict__ W1,
                 const float* __restrict__ b1,
                 const float* __restrict__ W2,
                 const float* __restrict__ b2,
                 float* __restrict__ out) {
    const float L2_A = -0.3845130f;  // log2(0.7660379)
    const float L2_B = -3.0448780f;  // log2(0.12117091)
    const float L2_C =  0.2780400f;  // log2(1.2125463)
    const float L2_D = -2.6783910f;  // log2(0.1562228)

    int t = blockIdx.x * blockDim.x + threadIdx.x;
    int n0 = t * 4;                       // first node of this thread's group
    if (n0 >= N_NODES) return;
    bool full = (n0 + 4 <= N_NODES);      // tail group handled scalar-ish

    // Front-batched independent loads (5 x LDG.128 when aligned).
    float xv[12];
    float2 acc[4];
    if (full) {
        const float4* xp = reinterpret_cast<const float4*>(x + 3 * n0);
        float4 xa = xp[0], xb = xp[1], xc = xp[2];
        xv[0]=xa.x; xv[1]=xa.y; xv[2]=xa.z; xv[3]=xa.w;
        xv[4]=xb.x; xv[5]=xb.y; xv[6]=xb.z; xv[7]=xb.w;
        xv[8]=xc.x; xv[9]=xc.y; xv[10]=xc.z; xv[11]=xc.w;
        const float4* ap = reinterpret_cast<const float4*>(&g_acc[2 * n0]);
        float4 g0 = ap[0], g1 = ap[1];
        acc[0] = make_float2(g0.x, g0.y);
        acc[1] = make_float2(g0.z, g0.w);
        acc[2] = make_float2(g1.x, g1.y);
        acc[3] = make_float2(g1.z, g1.w);
        float4 z4 = make_float4(0.f, 0.f, 0.f, 0.f);
        float4* apw = reinterpret_cast<float4*>(&g_acc[2 * n0]);
        apw[0] = z4; apw[1] = z4;
    } else {
        for (int k = 0; k < 4; k++) {
            int n = n0 + k;
            if (n < N_NODES) {
                xv[3*k+0] = x[3*n+0]; xv[3*k+1] = x[3*n+1]; xv[3*k+2] = x[3*n+2];
                acc[k] = make_float2(g_acc[2*n], g_acc[2*n+1]);
                g_acc[2*n] = 0.f; g_acc[2*n+1] = 0.f;
            } else {
                xv[3*k+0] = xv[3*k+1] = xv[3*k+2] = 0.f;
                acc[k] = make_float2(0.f, 0.f);
            }
        }
    }

    float w10 = W1[0], w11 = W1[1], w12 = W1[2];
    float w13 = W1[3], w14 = W1[4], w15 = W1[5];
    float bb0 = b1[0], bb1 = b1[1];
    float w22 = W2[2], w25 = W2[5], bb2 = b2[2];

    float res[12];
#pragma unroll
    for (int k = 0; k < 4; k++) {
        float x0 = xv[3*k+0], x1 = xv[3*k+1], x2 = xv[3*k+2];
        float z0 = fmaf(x0, w10, fmaf(x1, w12, fmaf(x2, w14, acc[k].x))) + bb0;
        float z1 = fmaf(x0, w11, fmaf(x1, w13, fmaf(x2, w15, acc[k].y))) + bb1;
        float mlp2 = fmaf(fmaxf(z0, 0.f), w22, fmaf(fmaxf(z1, 0.f), w25, bb2));

        float p1 = exp2f((x2 * (1.0f / 0.3038425f) + x1) * L2_A);
        float p2 = exp2f(x1 * L2_B) * (1.0f / -0.7256157f);
        float p3 = exp2f(x0 * L2_C);
        float n1 = fmaf(p1 + p2, p3, 0.12262904f);

        float expo = x2 + (x1 + (-3.283101f) - x0 * (1.0f / 0.79082423f)) * 0.31992579f;
        float inner = exp2f(expo * L2_D) + 1.4462701f;  // > 1.446 -> log > 0
        float n1n2 = 0.7872602f - sqrtf(__logf(inner));

        res[3*k+0] = n1 + x0;
        res[3*k+1] = (n1n2 - n1) + x1;
        res[3*k+2] = mlp2 + x2;
    }

    if (full) {
        float4* op = reinterpret_cast<float4*>(out + 3 * n0);
        op[0] = make_float4(res[0], res[1], res[2], res[3]);
        op[1] = make_float4(res[4], res[5], res[6], res[7]);
        op[2] = make_float4(res[8], res[9], res[10], res[11]);
    } else {
        for (int k = 0; k < 4; k++) {
            int n = n0 + k;
            if (n < N_NODES) {
                out[3*n+0] = res[3*k+0];
                out[3*n+1] = res[3*k+1];
                out[3*n+2] = res[3*k+2];
            }
        }
    }
}

extern "C" void kernel_launch(void* const* d_in, const int* in_sizes, int n_in,
                              void* d_out, int out_size) {
    // metadata order: x, edge_attr, u, W1, b1, W2, b2, edge_index, batch
    // edge_index is a (2, N_EDGES) int32 buffer (JAX x64-disabled coercion).
    const float* x          = (const float*)d_in[0];
    const float* edge_attr  = (const float*)d_in[1];
    const float* W1         = (const float*)d_in[3];
    const float* b1         = (const float*)d_in[4];
    const float* W2         = (const float*)d_in[5];
    const float* b2         = (const float*)d_in[6];
    const int*   edge_index = (const int*)d_in[7];
    float*       out        = (float*)d_out;

    const int* col = edge_index + N_EDGES;  // edge_index[1] row

    const int TB = 256;
    int edge_blocks = (N_EDGES + TB - 1) / TB;
    edge_kernel<<<edge_blocks, TB>>>(edge_attr, col, W1);

    const int NTB = 128;
    int node_groups = (N_NODES + 3) / 4;                 // 4 nodes per thread
    int node_blocks = (node_groups + NTB - 1) / NTB;
    node_kernel<<<node_blocks, NTB>>>(x, W1, b1, W2, b2, out);
}